// round 1
// baseline (speedup 1.0000x reference)
#include <cuda_runtime.h>

// ---------------- problem constants ----------------
#define BT    4096        // B*T
#define SEQT  2048        // T
#define DIM   1024        // D
#define T3D   3072        // 3*D
#define DIFF  2048        // DI
#define NL    8           // layers
#define NVOC  32000       // vocab

// ---------------- scratch (device globals; no allocation APIs) ----------------
__device__ float g_x[BT * DIM];       // residual stream     16 MB
__device__ float g_h[BT * DIM];       // normed / attn out   16 MB
__device__ float g_qkv[BT * T3D];     // qkv                 48 MB
__device__ float g_gate[BT * DIFF];   // gate / mlp inter    32 MB

// ---------------- packed fp32x2 helpers (sm_103a) ----------------
__device__ __forceinline__ unsigned long long pk2(float x, float y) {
    unsigned long long r;
    asm("mov.b64 %0, {%1, %2};" : "=l"(r) : "f"(x), "f"(y));
    return r;
}
__device__ __forceinline__ float2 upk2(unsigned long long v) {
    float2 f;
    asm("mov.b64 {%0, %1}, %2;" : "=f"(f.x), "=f"(f.y) : "l"(v));
    return f;
}
__device__ __forceinline__ void fma2(unsigned long long& d, unsigned long long a, unsigned long long b) {
    asm("fma.rn.f32x2 %0, %1, %2, %0;" : "+l"(d) : "l"(a), "l"(b));
}

__device__ __forceinline__ float silu_f(float x) { return x / (1.f + __expf(-x)); }

// ---------------- epilogues ----------------
// EPI 0: C = acc
// EPI 1: C = C + acc                (fused residual add)
// EPI 2: C = silu(C) * acc          (C holds gate, acc is up)
template <int EPI>
__device__ __forceinline__ void epi_store(float* cp, const float* r) {
    float4 o0, o1;
    if (EPI == 0) {
        o0 = make_float4(r[0], r[1], r[2], r[3]);
        o1 = make_float4(r[4], r[5], r[6], r[7]);
    } else if (EPI == 1) {
        float4 a = *(const float4*)cp;
        float4 b = *(const float4*)(cp + 4);
        o0 = make_float4(a.x + r[0], a.y + r[1], a.z + r[2], a.w + r[3]);
        o1 = make_float4(b.x + r[4], b.y + r[5], b.z + r[6], b.w + r[7]);
    } else {
        float4 a = *(const float4*)cp;
        float4 b = *(const float4*)(cp + 4);
        o0 = make_float4(silu_f(a.x) * r[0], silu_f(a.y) * r[1],
                         silu_f(a.z) * r[2], silu_f(a.w) * r[3]);
        o1 = make_float4(silu_f(b.x) * r[4], silu_f(b.y) * r[5],
                         silu_f(b.z) * r[6], silu_f(b.w) * r[7]);
    }
    *(float4*)cp       = o0;
    *(float4*)(cp + 4) = o1;
}

// ---------------- SGEMM: C[M,N] = A[M,K] @ W[N,K]^T  (fp32, f32x2 inner) ----------------
// Requires: M % 128 == 0, N % 128 == 0, K % 8 == 0.
// Block: 256 threads, 128x128 tile, BK=8, each thread 8x8 (as 4x8 packed M-pairs).
template <int EPI>
__global__ void __launch_bounds__(256) gemm_kernel(
    const float* __restrict__ A, const float* __restrict__ W,
    float* __restrict__ C, int N, int K)
{
    __shared__ float As[8][128];
    __shared__ float Ws[8][128];
    const int tid  = threadIdx.x;
    const int tx   = tid & 15;       // 0..15 -> 8 cols each
    const int ty   = tid >> 4;       // 0..15 -> 8 rows each
    const int lrow = tid >> 1;       // 0..127
    const int lcol = (tid & 1) << 2; // 0 or 4

    const float* Ap = A + (long long)(blockIdx.y * 128 + lrow) * K + lcol;
    const float* Wp = W + (long long)(blockIdx.x * 128 + lrow) * K + lcol;

    unsigned long long acc[4][8];
#pragma unroll
    for (int i = 0; i < 4; i++)
#pragma unroll
        for (int j = 0; j < 8; j++) acc[i][j] = 0ull;

    for (int k0 = 0; k0 < K; k0 += 8) {
        float4 av = *(const float4*)(Ap + k0);
        float4 wv = *(const float4*)(Wp + k0);
        As[lcol + 0][lrow] = av.x; As[lcol + 1][lrow] = av.y;
        As[lcol + 2][lrow] = av.z; As[lcol + 3][lrow] = av.w;
        Ws[lcol + 0][lrow] = wv.x; Ws[lcol + 1][lrow] = wv.y;
        Ws[lcol + 2][lrow] = wv.z; Ws[lcol + 3][lrow] = wv.w;
        __syncthreads();
#pragma unroll
        for (int k = 0; k < 8; k++) {
            unsigned long long a2[4];
#pragma unroll
            for (int i = 0; i < 4; i++)
                a2[i] = *(const unsigned long long*)&As[k][ty * 8 + i * 2];
            float4 w0 = *(const float4*)&Ws[k][tx * 8];
            float4 w1 = *(const float4*)&Ws[k][tx * 8 + 4];
            unsigned long long w2[8];
            w2[0] = pk2(w0.x, w0.x); w2[1] = pk2(w0.y, w0.y);
            w2[2] = pk2(w0.z, w0.z); w2[3] = pk2(w0.w, w0.w);
            w2[4] = pk2(w1.x, w1.x); w2[5] = pk2(w1.y, w1.y);
            w2[6] = pk2(w1.z, w1.z); w2[7] = pk2(w1.w, w1.w);
#pragma unroll
            for (int i = 0; i < 4; i++)
#pragma unroll
                for (int j = 0; j < 8; j++)
                    fma2(acc[i][j], a2[i], w2[j]);
        }
        __syncthreads();
    }

    const long long crow = (long long)(blockIdx.y * 128 + ty * 8);
    const int       ccol = blockIdx.x * 128 + tx * 8;
#pragma unroll
    for (int i = 0; i < 4; i++) {
        float r0[8], r1[8];
#pragma unroll
        for (int j = 0; j < 8; j++) {
            float2 t = upk2(acc[i][j]);
            r0[j] = t.x; r1[j] = t.y;
        }
        epi_store<EPI>(C + (crow + 2 * i)     * N + ccol, r0);
        epi_store<EPI>(C + (crow + 2 * i + 1) * N + ccol, r1);
    }
}

// ---------------- embedding gather ----------------
__global__ void embed_kernel(const int* __restrict__ idx,
                             const float* __restrict__ emb,
                             float* __restrict__ x)
{
    int row = blockIdx.x;
    int id  = idx[row];
    int t   = threadIdx.x;
    float4 v = *(const float4*)&emb[(long long)id * DIM + t * 4];
    *(float4*)&x[(long long)row * DIM + t * 4] = v;
}

// ---------------- rmsnorm (one CTA per row of 1024) ----------------
__global__ void rmsnorm_kernel(const float* __restrict__ x,
                               const float* __restrict__ w,
                               float* __restrict__ out)
{
    __shared__ float red[8];
    int row = blockIdx.x;
    int t   = threadIdx.x;
    const float4* xr = (const float4*)(x + (long long)row * DIM);
    float4 v = xr[t];
    float ss = v.x * v.x + v.y * v.y + v.z * v.z + v.w * v.w;
#pragma unroll
    for (int o = 16; o > 0; o >>= 1) ss += __shfl_xor_sync(0xffffffffu, ss, o);
    if ((t & 31) == 0) red[t >> 5] = ss;
    __syncthreads();
    float tot = red[0] + red[1] + red[2] + red[3] + red[4] + red[5] + red[6] + red[7];
    float r = rsqrtf(tot * (1.f / (float)DIM) + 1e-6f);
    float4 wv = ((const float4*)w)[t];
    float4 ov = make_float4(v.x * r * wv.x, v.y * r * wv.y, v.z * r * wv.z, v.w * r * wv.w);
    ((float4*)(out + (long long)row * DIM))[t] = ov;
}

// ---------------- fused causal flash attention (HD=64) ----------------
// grid (T/64, H, B), 256 threads. 64-query tile, 32-key chunks.
// Thread quad (lanes 4q..4q+3) owns query q: each lane computes 8 scores
// (keys j = dsub + 4*jj) and accumulates 16 output dims (d0 = dsub*16).
__global__ void __launch_bounds__(256) flash_kernel(const float* __restrict__ qkv,
                                                    float* __restrict__ y)
{
    __shared__ float Qs[64][68];
    __shared__ float Ks[32][68];
    __shared__ float Vs[32][68];
    const int qb  = blockIdx.x * 64;
    const int hh  = blockIdx.y;
    const int b   = blockIdx.z;
    const int tid = threadIdx.x;
    const int lane = tid & 31;
    const long long base = (long long)b * SEQT * T3D + hh * 64;

    // load + pre-scale Q tile (64 x 64)
#pragma unroll
    for (int i = 0; i < 4; i++) {
        int s4 = tid + i * 256;          // float4 slot 0..1023
        int r  = s4 >> 4;
        int c  = (s4 & 15) << 2;
        float4 v = *(const float4*)&qkv[base + (long long)(qb + r) * T3D + c];
        v.x *= 0.125f; v.y *= 0.125f; v.z *= 0.125f; v.w *= 0.125f;
        *(float4*)&Qs[r][c] = v;
    }

    const int q    = tid >> 2;
    const int qg   = qb + q;
    const int dsub = tid & 3;
    const int d0   = dsub << 4;
    const int lq4  = lane & ~3;

    float o[16];
#pragma unroll
    for (int i = 0; i < 16; i++) o[i] = 0.f;
    float m = -1e30f, l = 0.f;

    const int nch = qb / 32 + 2;   // key chunks covering 0..qb+63
    for (int kc = 0; kc < nch; kc++) {
        const int k0 = kc * 32;
        __syncthreads();           // protect Ks/Vs (and Qs on iter 0)
#pragma unroll
        for (int i = 0; i < 2; i++) {
            int s4 = tid + i * 256;      // float4 slot 0..511
            int r  = s4 >> 4;
            int c  = (s4 & 15) << 2;
            long long go = base + (long long)(k0 + r) * T3D + c;
            *(float4*)&Ks[r][c] = *(const float4*)&qkv[go + DIM];
            *(float4*)&Vs[r][c] = *(const float4*)&qkv[go + 2 * DIM];
        }
        __syncthreads();
        if (k0 <= qg) {   // warp-uniform: 8-aligned q ranges never straddle 32-key chunks
            float s[8];
#pragma unroll
            for (int jj = 0; jj < 8; jj++) s[jj] = 0.f;
#pragma unroll
            for (int d = 0; d < 64; d += 4) {
                float4 qv = *(const float4*)&Qs[q][d];
#pragma unroll
                for (int jj = 0; jj < 8; jj++) {
                    float4 kv = *(const float4*)&Ks[dsub + jj * 4][d];
                    s[jj] += qv.x * kv.x + qv.y * kv.y + qv.z * kv.z + qv.w * kv.w;
                }
            }
            float cmax = -1e30f;
#pragma unroll
            for (int jj = 0; jj < 8; jj++) {
                if (k0 + dsub + jj * 4 > qg) s[jj] = -1e30f;   // causal mask
                cmax = fmaxf(cmax, s[jj]);
            }
            cmax = fmaxf(cmax, __shfl_xor_sync(0xffffffffu, cmax, 1));
            cmax = fmaxf(cmax, __shfl_xor_sync(0xffffffffu, cmax, 2));
            const float mn   = fmaxf(m, cmax);
            const float corr = __expf(m - mn);
            float p[8];
            float ls = 0.f;
#pragma unroll
            for (int jj = 0; jj < 8; jj++) {
                p[jj] = (s[jj] < -1e29f) ? 0.f : __expf(s[jj] - mn);
                ls += p[jj];
            }
            ls += __shfl_xor_sync(0xffffffffu, ls, 1);
            ls += __shfl_xor_sync(0xffffffffu, ls, 2);
            l = l * corr + ls;
            m = mn;
#pragma unroll
            for (int i = 0; i < 16; i++) o[i] *= corr;
#pragma unroll
            for (int jj = 0; jj < 8; jj++) {
#pragma unroll
                for (int src = 0; src < 4; src++) {
                    float pv = __shfl_sync(0xffffffffu, p[jj], lq4 + src);
                    const float* vr = &Vs[src + jj * 4][d0];
#pragma unroll
                    for (int dd = 0; dd < 16; dd += 4) {
                        float4 vv = *(const float4*)&vr[dd];
                        o[dd]     += pv * vv.x;
                        o[dd + 1] += pv * vv.y;
                        o[dd + 2] += pv * vv.z;
                        o[dd + 3] += pv * vv.w;
                    }
                }
            }
        }
    }
    const float inv = 1.f / l;
    float* yr = y + ((long long)b * SEQT + qg) * DIM + hh * 64 + d0;
#pragma unroll
    for (int dd = 0; dd < 16; dd += 4) {
        float4 ov = make_float4(o[dd] * inv, o[dd + 1] * inv, o[dd + 2] * inv, o[dd + 3] * inv);
        *(float4*)&yr[dd] = ov;
    }
}

// ---------------- launch ----------------
extern "C" void kernel_launch(void* const* d_in, const int* in_sizes, int n_in,
                              void* d_out, int out_size)
{
    (void)in_sizes; (void)n_in; (void)out_size;
    const int*   idx  = (const int*)d_in[0];
    const float* emb  = (const float*)d_in[1];
    const float* ln1  = (const float*)d_in[2];
    const float* qkvw = (const float*)d_in[3];
    const float* ow   = (const float*)d_in[4];
    const float* ln2  = (const float*)d_in[5];
    const float* gw   = (const float*)d_in[6];
    const float* uw   = (const float*)d_in[7];
    const float* dw   = (const float*)d_in[8];
    const float* lnf  = (const float*)d_in[9];

    float *x, *h, *qkv, *gate;
    cudaGetSymbolAddress((void**)&x,    g_x);
    cudaGetSymbolAddress((void**)&h,    g_h);
    cudaGetSymbolAddress((void**)&qkv,  g_qkv);
    cudaGetSymbolAddress((void**)&gate, g_gate);

    embed_kernel<<<BT, 256>>>(idx, emb, x);

    for (int l = 0; l < NL; l++) {
        rmsnorm_kernel<<<BT, 256>>>(x, ln1 + (long long)l * DIM, h);
        gemm_kernel<0><<<dim3(T3D / 128, BT / 128), 256>>>(
            h, qkvw + (long long)l * T3D * DIM, qkv, T3D, DIM);
        flash_kernel<<<dim3(SEQT / 64, 16, 2), 256>>>(qkv, h);
        gemm_kernel<1><<<dim3(DIM / 128, BT / 128), 256>>>(
            h, ow + (long long)l * DIM * DIM, x, DIM, DIM);
        rmsnorm_kernel<<<BT, 256>>>(x, ln2 + (long long)l * DIM, h);
        gemm_kernel<0><<<dim3(DIFF / 128, BT / 128), 256>>>(
            h, gw + (long long)l * DIFF * DIM, gate, DIFF, DIM);
        gemm_kernel<2><<<dim3(DIFF / 128, BT / 128), 256>>>(
            h, uw + (long long)l * DIFF * DIM, gate, DIFF, DIM);
        gemm_kernel<1><<<dim3(DIM / 128, BT / 128), 256>>>(
            gate, dw + (long long)l * DIM * DIFF, x, DIM, DIFF);
    }

    rmsnorm_kernel<<<BT, 256>>>(x, lnf, h);
    gemm_kernel<0><<<dim3(NVOC / 128, BT / 128), 256>>>(
        h, emb, (float*)d_out, NVOC, DIM);
}

// round 3
// speedup vs baseline: 1.5022x; 1.5022x over previous
#include <cuda_runtime.h>
#include <cuda_bf16.h>
#include <stdint.h>

// ---------------- problem constants ----------------
#define BT    4096        // B*T
#define SEQT  2048        // T
#define DIM   1024        // D
#define T3D   3072        // 3*D
#define DIFF  2048        // DI
#define NL    8           // layers
#define NVOC  32000       // vocab

// ---------------- scratch ----------------
__device__ float g_x[BT * DIM];
__device__ float g_h[BT * DIM];
__device__ float g_qkv[BT * T3D];
__device__ float g_gate[BT * DIFF];

// ---------------- helpers ----------------
__device__ __forceinline__ uint32_t smem_u32(const void* p) {
    uint32_t a;
    asm("{ .reg .u64 t; cvta.to.shared.u64 t, %1; cvt.u32.u64 %0, t; }" : "=r"(a) : "l"(p));
    return a;
}
__device__ __forceinline__ void ldm4(uint32_t* r, uint32_t a) {
    asm volatile("ldmatrix.sync.aligned.m8n8.x4.shared.b16 {%0,%1,%2,%3}, [%4];"
                 : "=r"(r[0]), "=r"(r[1]), "=r"(r[2]), "=r"(r[3]) : "r"(a));
}
__device__ __forceinline__ void mma16816(float* d, const uint32_t* a, const uint32_t* b) {
    asm volatile(
        "mma.sync.aligned.m16n8k16.row.col.f32.bf16.bf16.f32 "
        "{%0,%1,%2,%3}, {%4,%5,%6,%7}, {%8,%9}, {%0,%1,%2,%3};"
        : "+f"(d[0]), "+f"(d[1]), "+f"(d[2]), "+f"(d[3])
        : "r"(a[0]), "r"(a[1]), "r"(a[2]), "r"(a[3]), "r"(b[0]), "r"(b[1]));
}

__device__ __forceinline__ uint32_t pkbf2(float x, float y) {
    __nv_bfloat162 h = __floats2bfloat162_rn(x, y);
    return *reinterpret_cast<uint32_t*>(&h);
}
// 8 fp32 -> 16B of bf16 hi + 16B of bf16 lo
__device__ __forceinline__ void split8_sts(float4 f0, float4 f1,
                                           uint32_t addr_h, uint32_t addr_l) {
    float xs[8] = {f0.x, f0.y, f0.z, f0.w, f1.x, f1.y, f1.z, f1.w};
    uint32_t H[4], L[4];
#pragma unroll
    for (int i = 0; i < 4; i++) {
        float a = xs[2 * i], b = xs[2 * i + 1];
        float ah = __bfloat162float(__float2bfloat16(a));
        float bh = __bfloat162float(__float2bfloat16(b));
        H[i] = pkbf2(ah, bh);
        L[i] = pkbf2(a - ah, b - bh);
    }
    asm volatile("st.shared.v4.b32 [%0], {%1,%2,%3,%4};"
                 :: "r"(addr_h), "r"(H[0]), "r"(H[1]), "r"(H[2]), "r"(H[3]) : "memory");
    asm volatile("st.shared.v4.b32 [%0], {%1,%2,%3,%4};"
                 :: "r"(addr_l), "r"(L[0]), "r"(L[1]), "r"(L[2]), "r"(L[3]) : "memory");
}

__device__ __forceinline__ float silu_f(float x) { return x / (1.f + __expf(-x)); }

// EPI 0: C = acc ; EPI 1: C += acc ; EPI 2: C = silu(C) * acc
template <int EPI>
__device__ __forceinline__ void epi2(float* p, float x, float y) {
    if (EPI == 1) {
        float2 c = *(const float2*)p;
        x += c.x; y += c.y;
    } else if (EPI == 2) {
        float2 c = *(const float2*)p;
        x = silu_f(c.x) * x; y = silu_f(c.y) * y;
    }
    *(float2*)p = make_float2(x, y);
}

// ============ mma.sync GEMM: C[M,N] = A[M,K] @ W[N,K]^T (fp32, bf16 hi/lo 3-pass) ============
// CTA tile 128x128, BK=32, 512 threads = 16 warps (4x4, warp tile 32x32).
// SMEM row (128B, SW128-swizzled): [s0 hi 32B][s0 lo 32B][s1 hi 32B][s1 lo 32B]
// A buf 16KB @0, B buf 16KB @16K, double buffered (stride 32K). Requires M%128==N%128==K%32==0.
template <int EPI>
__global__ void __launch_bounds__(512, 1) gemm_mma(
    const float* __restrict__ A, const float* __restrict__ W,
    float* __restrict__ C, int N, int K)
{
    extern __shared__ char dsm_raw[];
    char* dsm = (char*)(((uintptr_t)dsm_raw + 1023) & ~(uintptr_t)1023);
    const uint32_t sb = smem_u32(dsm);

    const int tid  = threadIdx.x;
    const int wid  = tid >> 5;
    const int lane = tid & 31;
    const int m0 = blockIdx.y * 128;
    const int n0 = blockIdx.x * 128;

    // ---- producer mapping: thread = (row, 8-float k-chunk) ----
    const int pr = tid >> 2;
    const int pc = tid & 3;
    const float* Ag = A + (long long)(m0 + pr) * K + pc * 8;
    const float* Bg = W + (long long)(n0 + pr) * K + pc * 8;
    const uint32_t pxr = (uint32_t)(pr & 7) << 4;
    const uint32_t chi = (uint32_t)((pc >> 1) * 64 + (pc & 1) * 16);
    const uint32_t pA_h = sb + pr * 128 + (chi ^ pxr);
    const uint32_t pA_l = sb + pr * 128 + ((chi + 32) ^ pxr);
    const uint32_t pB_h = pA_h + 16384u;
    const uint32_t pB_l = pA_l + 16384u;

    // ---- consumer mapping ----
    const int wm = (wid >> 2) * 32;
    const int wn = (wid & 3) * 32;
    const int lrow = ((lane >> 3) & 1) * 8 + (lane & 7);
    const uint32_t lcol = ((uint32_t)lane >> 4) * 16;
    uint32_t aRow[2], aXor[2], bRow[2], bXor[2];
#pragma unroll
    for (int t = 0; t < 2; t++) {
        int ra = wm + t * 16 + lrow;
        aRow[t] = sb + (uint32_t)ra * 128; aXor[t] = (uint32_t)(ra & 7) << 4;
        int rb = wn + t * 16 + lrow;
        bRow[t] = sb + 16384u + (uint32_t)rb * 128; bXor[t] = (uint32_t)(rb & 7) << 4;
    }

    float acc[2][4][4];
#pragma unroll
    for (int i = 0; i < 2; i++)
#pragma unroll
        for (int j = 0; j < 4; j++)
#pragma unroll
            for (int k = 0; k < 4; k++) acc[i][j][k] = 0.f;

    const int NT = K >> 5;

    // prologue: slab 0 -> buffer 0
    {
        float4 a0 = *(const float4*)Ag, a1 = *(const float4*)(Ag + 4);
        float4 b0 = *(const float4*)Bg, b1 = *(const float4*)(Bg + 4);
        split8_sts(a0, a1, pA_h, pA_l);
        split8_sts(b0, b1, pB_h, pB_l);
    }
    __syncthreads();

    for (int kt = 0; kt < NT; kt++) {
        const uint32_t buf = (kt & 1) ? 32768u : 0u;
        const bool more = (kt + 1 < NT);
        float4 a0, a1, b0, b1;
        if (more) {
            const int ko = (kt + 1) * 32;
            a0 = *(const float4*)(Ag + ko); a1 = *(const float4*)(Ag + ko + 4);
            b0 = *(const float4*)(Bg + ko); b1 = *(const float4*)(Bg + ko + 4);
        }
#pragma unroll
        for (int s = 0; s < 2; s++) {
            const uint32_t cb = (uint32_t)s * 64;
            uint32_t ah[2][4], al[2][4], bh[2][4], bl[2][4];
#pragma unroll
            for (int t = 0; t < 2; t++) {
                ldm4(ah[t], buf + aRow[t] + ((cb + lcol) ^ aXor[t]));
                ldm4(al[t], buf + aRow[t] + ((cb + 32 + lcol) ^ aXor[t]));
                ldm4(bh[t], buf + bRow[t] + ((cb + lcol) ^ bXor[t]));
                ldm4(bl[t], buf + bRow[t] + ((cb + 32 + lcol) ^ bXor[t]));
            }
#pragma unroll
            for (int mt = 0; mt < 2; mt++)
#pragma unroll
                for (int n8 = 0; n8 < 4; n8++) {
                    uint32_t bfh[2] = { bh[n8 >> 1][n8 & 1], bh[n8 >> 1][(n8 & 1) + 2] };
                    uint32_t bfl[2] = { bl[n8 >> 1][n8 & 1], bl[n8 >> 1][(n8 & 1) + 2] };
                    mma16816(acc[mt][n8], ah[mt], bfh);
                    mma16816(acc[mt][n8], ah[mt], bfl);
                    mma16816(acc[mt][n8], al[mt], bfh);
                }
        }
        __syncthreads();
        if (more) {
            const uint32_t o = buf ^ 32768u;
            split8_sts(a0, a1, pA_h + o, pA_l + o);
            split8_sts(b0, b1, pB_h + o, pB_l + o);
        }
        __syncthreads();
    }

    // ---- epilogue (register fragments -> gmem) ----
    const int er = lane >> 2;
    const int ec = (lane & 3) * 2;
#pragma unroll
    for (int mt = 0; mt < 2; mt++) {
        const int row = m0 + wm + mt * 16 + er;
#pragma unroll
        for (int n8 = 0; n8 < 4; n8++) {
            const int col = n0 + wn + n8 * 8 + ec;
            float* p = C + (long long)row * N + col;
            epi2<EPI>(p,                    acc[mt][n8][0], acc[mt][n8][1]);
            epi2<EPI>(p + (long long)8 * N, acc[mt][n8][2], acc[mt][n8][3]);
        }
    }
}

// ---------------- embedding gather ----------------
__global__ void embed_kernel(const int* __restrict__ idx,
                             const float* __restrict__ emb,
                             float* __restrict__ x)
{
    int row = blockIdx.x;
    int id  = idx[row];
    int t   = threadIdx.x;
    float4 v = *(const float4*)&emb[(long long)id * DIM + t * 4];
    *(float4*)&x[(long long)row * DIM + t * 4] = v;
}

// ---------------- rmsnorm ----------------
__global__ void rmsnorm_kernel(const float* __restrict__ x,
                               const float* __restrict__ w,
                               float* __restrict__ out)
{
    __shared__ float red[8];
    int row = blockIdx.x;
    int t   = threadIdx.x;
    const float4* xr = (const float4*)(x + (long long)row * DIM);
    float4 v = xr[t];
    float ss = v.x * v.x + v.y * v.y + v.z * v.z + v.w * v.w;
#pragma unroll
    for (int o = 16; o > 0; o >>= 1) ss += __shfl_xor_sync(0xffffffffu, ss, o);
    if ((t & 31) == 0) red[t >> 5] = ss;
    __syncthreads();
    float tot = red[0] + red[1] + red[2] + red[3] + red[4] + red[5] + red[6] + red[7];
    float r = rsqrtf(tot * (1.f / (float)DIM) + 1e-6f);
    float4 wv = ((const float4*)w)[t];
    float4 ov = make_float4(v.x * r * wv.x, v.y * r * wv.y, v.z * r * wv.z, v.w * r * wv.w);
    ((float4*)(out + (long long)row * DIM))[t] = ov;
}

// ---------------- fused causal flash attention (HD=64) ----------------
__global__ void __launch_bounds__(256) flash_kernel(const float* __restrict__ qkv,
                                                    float* __restrict__ y)
{
    __shared__ float Qs[64][68];
    __shared__ float Ks[32][68];
    __shared__ float Vs[32][68];
    const int qb  = blockIdx.x * 64;
    const int hh  = blockIdx.y;
    const int b   = blockIdx.z;
    const int tid = threadIdx.x;
    const int lane = tid & 31;
    const long long base = (long long)b * SEQT * T3D + hh * 64;

#pragma unroll
    for (int i = 0; i < 4; i++) {
        int s4 = tid + i * 256;
        int r  = s4 >> 4;
        int c  = (s4 & 15) << 2;
        float4 v = *(const float4*)&qkv[base + (long long)(qb + r) * T3D + c];
        v.x *= 0.125f; v.y *= 0.125f; v.z *= 0.125f; v.w *= 0.125f;
        *(float4*)&Qs[r][c] = v;
    }

    const int q    = tid >> 2;
    const int qg   = qb + q;
    const int dsub = tid & 3;
    const int d0   = dsub << 4;
    const int lq4  = lane & ~3;

    float o[16];
#pragma unroll
    for (int i = 0; i < 16; i++) o[i] = 0.f;
    float m = -1e30f, l = 0.f;

    const int nch = qb / 32 + 2;
    for (int kc = 0; kc < nch; kc++) {
        const int k0 = kc * 32;
        __syncthreads();
#pragma unroll
        for (int i = 0; i < 2; i++) {
            int s4 = tid + i * 256;
            int r  = s4 >> 4;
            int c  = (s4 & 15) << 2;
            long long go = base + (long long)(k0 + r) * T3D + c;
            *(float4*)&Ks[r][c] = *(const float4*)&qkv[go + DIM];
            *(float4*)&Vs[r][c] = *(const float4*)&qkv[go + 2 * DIM];
        }
        __syncthreads();
        if (k0 <= qg) {
            float s[8];
#pragma unroll
            for (int jj = 0; jj < 8; jj++) s[jj] = 0.f;
#pragma unroll
            for (int d = 0; d < 64; d += 4) {
                float4 qv = *(const float4*)&Qs[q][d];
#pragma unroll
                for (int jj = 0; jj < 8; jj++) {
                    float4 kv = *(const float4*)&Ks[dsub + jj * 4][d];
                    s[jj] += qv.x * kv.x + qv.y * kv.y + qv.z * kv.z + qv.w * kv.w;
                }
            }
            float cmax = -1e30f;
#pragma unroll
            for (int jj = 0; jj < 8; jj++) {
                if (k0 + dsub + jj * 4 > qg) s[jj] = -1e30f;
                cmax = fmaxf(cmax, s[jj]);
            }
            cmax = fmaxf(cmax, __shfl_xor_sync(0xffffffffu, cmax, 1));
            cmax = fmaxf(cmax, __shfl_xor_sync(0xffffffffu, cmax, 2));
            const float mn   = fmaxf(m, cmax);
            const float corr = __expf(m - mn);
            float p[8];
            float ls = 0.f;
#pragma unroll
            for (int jj = 0; jj < 8; jj++) {
                p[jj] = (s[jj] < -1e29f) ? 0.f : __expf(s[jj] - mn);
                ls += p[jj];
            }
            ls += __shfl_xor_sync(0xffffffffu, ls, 1);
            ls += __shfl_xor_sync(0xffffffffu, ls, 2);
            l = l * corr + ls;
            m = mn;
#pragma unroll
            for (int i = 0; i < 16; i++) o[i] *= corr;
#pragma unroll
            for (int jj = 0; jj < 8; jj++) {
#pragma unroll
                for (int src = 0; src < 4; src++) {
                    float pv = __shfl_sync(0xffffffffu, p[jj], lq4 + src);
                    const float* vr = &Vs[src + jj * 4][d0];
#pragma unroll
                    for (int dd = 0; dd < 16; dd += 4) {
                        float4 vv = *(const float4*)&vr[dd];
                        o[dd]     += pv * vv.x;
                        o[dd + 1] += pv * vv.y;
                        o[dd + 2] += pv * vv.z;
                        o[dd + 3] += pv * vv.w;
                    }
                }
            }
        }
    }
    const float inv = 1.f / l;
    float* yr = y + ((long long)b * SEQT + qg) * DIM + hh * 64 + d0;
#pragma unroll
    for (int dd = 0; dd < 16; dd += 4) {
        float4 ov = make_float4(o[dd] * inv, o[dd + 1] * inv, o[dd + 2] * inv, o[dd + 3] * inv);
        *(float4*)&yr[dd] = ov;
    }
}

// ---------------- launch ----------------
#define GEMM_SMEM (65536 + 1024)

extern "C" void kernel_launch(void* const* d_in, const int* in_sizes, int n_in,
                              void* d_out, int out_size)
{
    (void)in_sizes; (void)n_in; (void)out_size;
    const int*   idx  = (const int*)d_in[0];
    const float* emb  = (const float*)d_in[1];
    const float* ln1  = (const float*)d_in[2];
    const float* qkvw = (const float*)d_in[3];
    const float* ow   = (const float*)d_in[4];
    const float* ln2  = (const float*)d_in[5];
    const float* gw   = (const float*)d_in[6];
    const float* uw   = (const float*)d_in[7];
    const float* dw   = (const float*)d_in[8];
    const float* lnf  = (const float*)d_in[9];

    float *x, *h, *qkv, *gate;
    cudaGetSymbolAddress((void**)&x,    g_x);
    cudaGetSymbolAddress((void**)&h,    g_h);
    cudaGetSymbolAddress((void**)&qkv,  g_qkv);
    cudaGetSymbolAddress((void**)&gate, g_gate);

    cudaFuncSetAttribute(gemm_mma<0>, cudaFuncAttributeMaxDynamicSharedMemorySize, GEMM_SMEM);
    cudaFuncSetAttribute(gemm_mma<1>, cudaFuncAttributeMaxDynamicSharedMemorySize, GEMM_SMEM);
    cudaFuncSetAttribute(gemm_mma<2>, cudaFuncAttributeMaxDynamicSharedMemorySize, GEMM_SMEM);

    embed_kernel<<<BT, 256>>>(idx, emb, x);

    for (int l = 0; l < NL; l++) {
        rmsnorm_kernel<<<BT, 256>>>(x, ln1 + (long long)l * DIM, h);
        gemm_mma<0><<<dim3(T3D / 128, BT / 128), 512, GEMM_SMEM>>>(
            h, qkvw + (long long)l * T3D * DIM, qkv, T3D, DIM);
        flash_kernel<<<dim3(SEQT / 64, 16, 2), 256>>>(qkv, h);
        gemm_mma<1><<<dim3(DIM / 128, BT / 128), 512, GEMM_SMEM>>>(
            h, ow + (long long)l * DIM * DIM, x, DIM, DIM);
        rmsnorm_kernel<<<BT, 256>>>(x, ln2 + (long long)l * DIM, h);
        gemm_mma<0><<<dim3(DIFF / 128, BT / 128), 512, GEMM_SMEM>>>(
            h, gw + (long long)l * DIFF * DIM, gate, DIFF, DIM);
        gemm_mma<2><<<dim3(DIFF / 128, BT / 128), 512, GEMM_SMEM>>>(
            h, uw + (long long)l * DIFF * DIM, gate, DIFF, DIM);
        gemm_mma<1><<<dim3(DIM / 128, BT / 128), 512, GEMM_SMEM>>>(
            gate, dw + (long long)l * DIM * DIFF, x, DIM, DIFF);
    }

    rmsnorm_kernel<<<BT, 256>>>(x, lnf, h);
    gemm_mma<0><<<dim3(NVOC / 128, BT / 128), 512, GEMM_SMEM>>>(
        h, emb, (float*)d_out, NVOC, DIM);
}

// round 4
// speedup vs baseline: 1.5645x; 1.0415x over previous
#include <cuda_runtime.h>
#include <cuda_bf16.h>
#include <stdint.h>

// ---------------- problem constants ----------------
#define BT    4096        // B*T
#define SEQT  2048        // T
#define DIM   1024        // D
#define T3D   3072        // 3*D
#define DIFF  2048        // DI
#define NL    8           // layers
#define NVOC  32000       // vocab

#define QKV_WN ((long long)NL * T3D * DIM)
#define O_WN   ((long long)NL * DIM * DIM)
#define G_WN   ((long long)NL * DIFF * DIM)
#define D_WN   ((long long)NL * DIM * DIFF)
#define E_WN   ((long long)NVOC * DIM)

// ---------------- scratch ----------------
__device__ float g_x[BT * DIM];               // residual (fp32)
__device__ float g_qkv[BT * T3D];             // qkv (fp32)
__device__ float g_gate[BT * DIFF];           // gate pre-act (fp32)
__device__ __nv_bfloat16 g_hh[BT * DIM],  g_hl[BT * DIM];    // activation hi/lo
__device__ __nv_bfloat16 g_2h[BT * DIFF], g_2l[BT * DIFF];   // mlp mid hi/lo
// pre-split weights (bf16 hi/lo)
__device__ __nv_bfloat16 g_qkvh[QKV_WN], g_qkvl[QKV_WN];
__device__ __nv_bfloat16 g_owh[O_WN],    g_owl[O_WN];
__device__ __nv_bfloat16 g_gwh[G_WN],    g_gwl[G_WN];
__device__ __nv_bfloat16 g_uwh[G_WN],    g_uwl[G_WN];
__device__ __nv_bfloat16 g_dwh[D_WN],    g_dwl[D_WN];
__device__ __nv_bfloat16 g_embh[E_WN],   g_embl[E_WN];

// ---------------- helpers ----------------
__device__ __forceinline__ uint32_t smem_u32(const void* p) {
    uint32_t a;
    asm("{ .reg .u64 t; cvta.to.shared.u64 t, %1; cvt.u32.u64 %0, t; }" : "=r"(a) : "l"(p));
    return a;
}
__device__ __forceinline__ void ldm4(uint32_t* r, uint32_t a) {
    asm volatile("ldmatrix.sync.aligned.m8n8.x4.shared.b16 {%0,%1,%2,%3}, [%4];"
                 : "=r"(r[0]), "=r"(r[1]), "=r"(r[2]), "=r"(r[3]) : "r"(a));
}
__device__ __forceinline__ void mma16816(float* d, const uint32_t* a, const uint32_t* b) {
    asm volatile(
        "mma.sync.aligned.m16n8k16.row.col.f32.bf16.bf16.f32 "
        "{%0,%1,%2,%3}, {%4,%5,%6,%7}, {%8,%9}, {%0,%1,%2,%3};"
        : "+f"(d[0]), "+f"(d[1]), "+f"(d[2]), "+f"(d[3])
        : "r"(a[0]), "r"(a[1]), "r"(a[2]), "r"(a[3]), "r"(b[0]), "r"(b[1]));
}
__device__ __forceinline__ void cpa16(uint32_t d, const void* s) {
    asm volatile("cp.async.cg.shared.global [%0], [%1], 16;" :: "r"(d), "l"(s));
}
__device__ __forceinline__ uint32_t pkbf2(float x, float y) {
    __nv_bfloat162 h = __floats2bfloat162_rn(x, y);
    return *reinterpret_cast<uint32_t*>(&h);
}
// (x,y) fp32 -> packed bf16 hi pair + packed bf16 lo pair
__device__ __forceinline__ void split2(float x, float y, uint32_t& h, uint32_t& l) {
    __nv_bfloat162 hb = __floats2bfloat162_rn(x, y);
    h = *reinterpret_cast<uint32_t*>(&hb);
    l = pkbf2(x - __bfloat162float(hb.x), y - __bfloat162float(hb.y));
}
__device__ __forceinline__ float silu_f(float x) { return x / (1.f + __expf(-x)); }

// ---------------- weight split: fp32 -> bf16 hi/lo ----------------
__global__ void split_kernel(const float* __restrict__ s,
                             __nv_bfloat16* __restrict__ H,
                             __nv_bfloat16* __restrict__ L, long long n)
{
    long long i = ((long long)blockIdx.x * 256 + threadIdx.x) * 4;
    if (i >= n) return;
    float4 v = *(const float4*)(s + i);
    uint32_t h0, l0, h1, l1;
    split2(v.x, v.y, h0, l0);
    split2(v.z, v.w, h1, l1);
    *(uint2*)(H + i) = make_uint2(h0, h1);
    *(uint2*)(L + i) = make_uint2(l0, l1);
}

// EPI 0: C = acc ; EPI 1: C += acc ; EPI 2: OH/OL = split(silu(C) * acc)
template <int EPI>
__device__ __forceinline__ void epi2(float* __restrict__ C,
                                     __nv_bfloat16* __restrict__ OH,
                                     __nv_bfloat16* __restrict__ OL,
                                     long long off, float x, float y)
{
    if (EPI == 0) {
        *(float2*)(C + off) = make_float2(x, y);
    } else if (EPI == 1) {
        float2 c = *(const float2*)(C + off);
        *(float2*)(C + off) = make_float2(c.x + x, c.y + y);
    } else {
        float2 c = *(const float2*)(C + off);
        x = silu_f(c.x) * x;
        y = silu_f(c.y) * y;
        uint32_t h, l;
        split2(x, y, h, l);
        *(uint32_t*)(OH + off) = h;
        *(uint32_t*)(OL + off) = l;
    }
}

// ============ bf16 mma.sync GEMM, cp.async 4-stage pipeline ============
// C[M,N] = (Ah+Al)[M,K] @ (Wh+Wl)[N,K]^T, 3 passes (AhWh + AhWl + AlWh).
// CTA tile 128x128, BK=32, 512 threads = 16 warps (4x4, warp tile 32x32).
// SMEM stage 32KB: A tile 16KB @0, B tile 16KB @16K. Stage stride 32KB, 4 stages.
// Row (128B, SW128): [hi k0-15 |32B][lo k0-15 |32B][hi k16-31 |32B][lo k16-31 |32B]
template <int EPI>
__global__ void __launch_bounds__(512, 1) gemm_bf(
    const __nv_bfloat16* __restrict__ Ah, const __nv_bfloat16* __restrict__ Al,
    const __nv_bfloat16* __restrict__ Wh, const __nv_bfloat16* __restrict__ Wl,
    float* __restrict__ C, __nv_bfloat16* __restrict__ OH, __nv_bfloat16* __restrict__ OL,
    int N, int K)
{
    extern __shared__ char dsm_raw[];
    char* dsm = (char*)(((uintptr_t)dsm_raw + 1023) & ~(uintptr_t)1023);
    const uint32_t sb = smem_u32(dsm);

    const int tid = threadIdx.x;
    const int wid = tid >> 5;
    const int lane = tid & 31;
    const int m0 = blockIdx.y * 128;
    const int n0 = blockIdx.x * 128;

    // ---- producer mapping: 2 chunks (16B) per operand per thread ----
    const __nv_bfloat16* srcA[2];
    const __nv_bfloat16* srcB[2];
    uint32_t dstA[2], dstB[2];
#pragma unroll
    for (int i = 0; i < 2; i++) {
        int g = tid + 512 * i;
        int row = g >> 3;
        int c = g & 7;
        int koff = ((c >> 2) << 4) + ((c & 1) << 3);   // k-element offset within slab
        bool lov = (c & 2);
        srcA[i] = (lov ? Al : Ah) + (long long)(m0 + row) * K + koff;
        srcB[i] = (lov ? Wl : Wh) + (long long)(n0 + row) * K + koff;
        uint32_t d = (uint32_t)row * 128u + (((uint32_t)c * 16u) ^ ((uint32_t)(row & 7) << 4));
        dstA[i] = sb + d;
        dstB[i] = sb + 16384u + d;
    }

    // ---- consumer mapping ----
    const int wm = (wid >> 2) * 32;
    const int wn = (wid & 3) * 32;
    const int lrow = ((lane >> 3) & 1) * 8 + (lane & 7);
    const uint32_t lcol = ((uint32_t)lane >> 4) * 16;
    uint32_t aOff[2], aXor[2], bOff[2], bXor[2];
#pragma unroll
    for (int t = 0; t < 2; t++) {
        int ra = wm + t * 16 + lrow;
        aOff[t] = (uint32_t)ra * 128u; aXor[t] = (uint32_t)(ra & 7) << 4;
        int rb = wn + t * 16 + lrow;
        bOff[t] = 16384u + (uint32_t)rb * 128u; bXor[t] = (uint32_t)(rb & 7) << 4;
    }

    float acc[2][4][4];
#pragma unroll
    for (int i = 0; i < 2; i++)
#pragma unroll
        for (int j = 0; j < 4; j++)
#pragma unroll
            for (int k = 0; k < 4; k++) acc[i][j][k] = 0.f;

    const int NT = K >> 5;

    // ---- prologue: stages 0..2 ----
#pragma unroll
    for (int st = 0; st < 3; st++) {
        const uint32_t bo = (uint32_t)st * 32768u;
        const int ko = st * 32;
#pragma unroll
        for (int i = 0; i < 2; i++) {
            cpa16(dstA[i] + bo, srcA[i] + ko);
            cpa16(dstB[i] + bo, srcB[i] + ko);
        }
        asm volatile("cp.async.commit_group;" ::: "memory");
    }

    for (int kt = 0; kt < NT; kt++) {
        asm volatile("cp.async.wait_group 2;" ::: "memory");
        __syncthreads();
        const uint32_t buf = sb + (uint32_t)(kt & 3) * 32768u;

#pragma unroll
        for (int s = 0; s < 2; s++) {
            const uint32_t cb = (uint32_t)s * 64;
            uint32_t ah[2][4], al[2][4], bh[2][4], bl[2][4];
#pragma unroll
            for (int t = 0; t < 2; t++) {
                ldm4(ah[t], buf + aOff[t] + ((cb + lcol) ^ aXor[t]));
                ldm4(al[t], buf + aOff[t] + ((cb + 32 + lcol) ^ aXor[t]));
                ldm4(bh[t], buf + bOff[t] + ((cb + lcol) ^ bXor[t]));
                ldm4(bl[t], buf + bOff[t] + ((cb + 32 + lcol) ^ bXor[t]));
            }
#pragma unroll
            for (int mt = 0; mt < 2; mt++)
#pragma unroll
                for (int n8 = 0; n8 < 4; n8++) {
                    uint32_t bfh[2] = { bh[n8 >> 1][n8 & 1], bh[n8 >> 1][(n8 & 1) + 2] };
                    uint32_t bfl[2] = { bl[n8 >> 1][n8 & 1], bl[n8 >> 1][(n8 & 1) + 2] };
                    mma16816(acc[mt][n8], ah[mt], bfh);
                    mma16816(acc[mt][n8], ah[mt], bfl);
                    mma16816(acc[mt][n8], al[mt], bfh);
                }
        }

        const int nst = kt + 3;
        if (nst < NT) {
            const uint32_t bo = (uint32_t)(nst & 3) * 32768u;
            const int ko = nst * 32;
#pragma unroll
            for (int i = 0; i < 2; i++) {
                cpa16(dstA[i] + bo, srcA[i] + ko);
                cpa16(dstB[i] + bo, srcB[i] + ko);
            }
        }
        asm volatile("cp.async.commit_group;" ::: "memory");
    }

    // ---- epilogue ----
    const int er = lane >> 2;
    const int ec = (lane & 3) * 2;
#pragma unroll
    for (int mt = 0; mt < 2; mt++) {
        const int row = m0 + wm + mt * 16 + er;
#pragma unroll
        for (int n8 = 0; n8 < 4; n8++) {
            const int col = n0 + wn + n8 * 8 + ec;
            long long off = (long long)row * N + col;
            epi2<EPI>(C, OH, OL, off,                     acc[mt][n8][0], acc[mt][n8][1]);
            epi2<EPI>(C, OH, OL, off + (long long)8 * N,  acc[mt][n8][2], acc[mt][n8][3]);
        }
    }
}

// ---------------- embedding gather ----------------
__global__ void embed_kernel(const int* __restrict__ idx,
                             const float* __restrict__ emb,
                             float* __restrict__ x)
{
    int row = blockIdx.x;
    int id  = idx[row];
    int t   = threadIdx.x;
    float4 v = *(const float4*)&emb[(long long)id * DIM + t * 4];
    *(float4*)&x[(long long)row * DIM + t * 4] = v;
}

// ---------------- rmsnorm -> bf16 hi/lo ----------------
__global__ void rmsnorm_split_kernel(const float* __restrict__ x,
                                     const float* __restrict__ w,
                                     __nv_bfloat16* __restrict__ OH,
                                     __nv_bfloat16* __restrict__ OL)
{
    __shared__ float red[8];
    int row = blockIdx.x;
    int t   = threadIdx.x;
    const float4* xr = (const float4*)(x + (long long)row * DIM);
    float4 v = xr[t];
    float ss = v.x * v.x + v.y * v.y + v.z * v.z + v.w * v.w;
#pragma unroll
    for (int o = 16; o > 0; o >>= 1) ss += __shfl_xor_sync(0xffffffffu, ss, o);
    if ((t & 31) == 0) red[t >> 5] = ss;
    __syncthreads();
    float tot = red[0] + red[1] + red[2] + red[3] + red[4] + red[5] + red[6] + red[7];
    float r = rsqrtf(tot * (1.f / (float)DIM) + 1e-6f);
    float4 wv = ((const float4*)w)[t];
    float4 ov = make_float4(v.x * r * wv.x, v.y * r * wv.y, v.z * r * wv.z, v.w * r * wv.w);
    uint32_t h0, l0, h1, l1;
    split2(ov.x, ov.y, h0, l0);
    split2(ov.z, ov.w, h1, l1);
    ((uint2*)(OH + (long long)row * DIM))[t] = make_uint2(h0, h1);
    ((uint2*)(OL + (long long)row * DIM))[t] = make_uint2(l0, l1);
}

// ---------------- fused causal flash attention (HD=64), bf16 hi/lo out ----------------
__global__ void __launch_bounds__(256) flash_kernel(const float* __restrict__ qkv,
                                                    __nv_bfloat16* __restrict__ OH,
                                                    __nv_bfloat16* __restrict__ OL)
{
    __shared__ float Qs[64][68];
    __shared__ float Ks[32][68];
    __shared__ float Vs[32][68];
    const int qb  = blockIdx.x * 64;
    const int hh  = blockIdx.y;
    const int b   = blockIdx.z;
    const int tid = threadIdx.x;
    const int lane = tid & 31;
    const long long base = (long long)b * SEQT * T3D + hh * 64;

#pragma unroll
    for (int i = 0; i < 4; i++) {
        int s4 = tid + i * 256;
        int r  = s4 >> 4;
        int c  = (s4 & 15) << 2;
        float4 v = *(const float4*)&qkv[base + (long long)(qb + r) * T3D + c];
        v.x *= 0.125f; v.y *= 0.125f; v.z *= 0.125f; v.w *= 0.125f;
        *(float4*)&Qs[r][c] = v;
    }

    const int q    = tid >> 2;
    const int qg   = qb + q;
    const int dsub = tid & 3;
    const int d0   = dsub << 4;
    const int lq4  = lane & ~3;

    float o[16];
#pragma unroll
    for (int i = 0; i < 16; i++) o[i] = 0.f;
    float m = -1e30f, l = 0.f;

    const int nch = qb / 32 + 2;
    for (int kc = 0; kc < nch; kc++) {
        const int k0 = kc * 32;
        __syncthreads();
#pragma unroll
        for (int i = 0; i < 2; i++) {
            int s4 = tid + i * 256;
            int r  = s4 >> 4;
            int c  = (s4 & 15) << 2;
            long long go = base + (long long)(k0 + r) * T3D + c;
            *(float4*)&Ks[r][c] = *(const float4*)&qkv[go + DIM];
            *(float4*)&Vs[r][c] = *(const float4*)&qkv[go + 2 * DIM];
        }
        __syncthreads();
        if (k0 <= qg) {
            float s[8];
#pragma unroll
            for (int jj = 0; jj < 8; jj++) s[jj] = 0.f;
#pragma unroll
            for (int d = 0; d < 64; d += 4) {
                float4 qv = *(const float4*)&Qs[q][d];
#pragma unroll
                for (int jj = 0; jj < 8; jj++) {
                    float4 kv = *(const float4*)&Ks[dsub + jj * 4][d];
                    s[jj] += qv.x * kv.x + qv.y * kv.y + qv.z * kv.z + qv.w * kv.w;
                }
            }
            float cmax = -1e30f;
#pragma unroll
            for (int jj = 0; jj < 8; jj++) {
                if (k0 + dsub + jj * 4 > qg) s[jj] = -1e30f;
                cmax = fmaxf(cmax, s[jj]);
            }
            cmax = fmaxf(cmax, __shfl_xor_sync(0xffffffffu, cmax, 1));
            cmax = fmaxf(cmax, __shfl_xor_sync(0xffffffffu, cmax, 2));
            const float mn   = fmaxf(m, cmax);
            const float corr = __expf(m - mn);
            float p[8];
            float ls = 0.f;
#pragma unroll
            for (int jj = 0; jj < 8; jj++) {
                p[jj] = (s[jj] < -1e29f) ? 0.f : __expf(s[jj] - mn);
                ls += p[jj];
            }
            ls += __shfl_xor_sync(0xffffffffu, ls, 1);
            ls += __shfl_xor_sync(0xffffffffu, ls, 2);
            l = l * corr + ls;
            m = mn;
#pragma unroll
            for (int i = 0; i < 16; i++) o[i] *= corr;
#pragma unroll
            for (int jj = 0; jj < 8; jj++) {
#pragma unroll
                for (int src = 0; src < 4; src++) {
                    float pv = __shfl_sync(0xffffffffu, p[jj], lq4 + src);
                    const float* vr = &Vs[src + jj * 4][d0];
#pragma unroll
                    for (int dd = 0; dd < 16; dd += 4) {
                        float4 vv = *(const float4*)&vr[dd];
                        o[dd]     += pv * vv.x;
                        o[dd + 1] += pv * vv.y;
                        o[dd + 2] += pv * vv.z;
                        o[dd + 3] += pv * vv.w;
                    }
                }
            }
        }
    }
    const float inv = 1.f / l;
    uint32_t H[8], L[8];
#pragma unroll
    for (int dd = 0; dd < 16; dd += 2)
        split2(o[dd] * inv, o[dd + 1] * inv, H[dd >> 1], L[dd >> 1]);
    const long long off = ((long long)b * SEQT + qg) * DIM + hh * 64 + d0;
    *(uint4*)(OH + off)     = make_uint4(H[0], H[1], H[2], H[3]);
    *(uint4*)(OH + off + 8) = make_uint4(H[4], H[5], H[6], H[7]);
    *(uint4*)(OL + off)     = make_uint4(L[0], L[1], L[2], L[3]);
    *(uint4*)(OL + off + 8) = make_uint4(L[4], L[5], L[6], L[7]);
}

// ---------------- launch ----------------
#define GEMM_SMEM (4 * 32768 + 1024)

static inline void split_launch(const float* s, __nv_bfloat16* H, __nv_bfloat16* L, long long n) {
    split_kernel<<<(unsigned)((n / 4 + 255) / 256), 256>>>(s, H, L, n);
}

extern "C" void kernel_launch(void* const* d_in, const int* in_sizes, int n_in,
                              void* d_out, int out_size)
{
    (void)in_sizes; (void)n_in; (void)out_size;
    const int*   idx  = (const int*)d_in[0];
    const float* emb  = (const float*)d_in[1];
    const float* ln1  = (const float*)d_in[2];
    const float* qkvw = (const float*)d_in[3];
    const float* ow   = (const float*)d_in[4];
    const float* ln2  = (const float*)d_in[5];
    const float* gw   = (const float*)d_in[6];
    const float* uw   = (const float*)d_in[7];
    const float* dw   = (const float*)d_in[8];
    const float* lnf  = (const float*)d_in[9];

    float *x, *qkv, *gate;
    __nv_bfloat16 *hh, *hl, *a2h, *a2l;
    __nv_bfloat16 *qkvh, *qkvl, *owh, *owl, *gwh, *gwl, *uwh, *uwl, *dwh, *dwl, *embh, *embl;
    cudaGetSymbolAddress((void**)&x,    g_x);
    cudaGetSymbolAddress((void**)&qkv,  g_qkv);
    cudaGetSymbolAddress((void**)&gate, g_gate);
    cudaGetSymbolAddress((void**)&hh,   g_hh);
    cudaGetSymbolAddress((void**)&hl,   g_hl);
    cudaGetSymbolAddress((void**)&a2h,  g_2h);
    cudaGetSymbolAddress((void**)&a2l,  g_2l);
    cudaGetSymbolAddress((void**)&qkvh, g_qkvh);
    cudaGetSymbolAddress((void**)&qkvl, g_qkvl);
    cudaGetSymbolAddress((void**)&owh,  g_owh);
    cudaGetSymbolAddress((void**)&owl,  g_owl);
    cudaGetSymbolAddress((void**)&gwh,  g_gwh);
    cudaGetSymbolAddress((void**)&gwl,  g_gwl);
    cudaGetSymbolAddress((void**)&uwh,  g_uwh);
    cudaGetSymbolAddress((void**)&uwl,  g_uwl);
    cudaGetSymbolAddress((void**)&dwh,  g_dwh);
    cudaGetSymbolAddress((void**)&dwl,  g_dwl);
    cudaGetSymbolAddress((void**)&embh, g_embh);
    cudaGetSymbolAddress((void**)&embl, g_embl);

    cudaFuncSetAttribute(gemm_bf<0>, cudaFuncAttributeMaxDynamicSharedMemorySize, GEMM_SMEM);
    cudaFuncSetAttribute(gemm_bf<1>, cudaFuncAttributeMaxDynamicSharedMemorySize, GEMM_SMEM);
    cudaFuncSetAttribute(gemm_bf<2>, cudaFuncAttributeMaxDynamicSharedMemorySize, GEMM_SMEM);

    // pre-split all weights (once per launch; ~130us bandwidth-bound)
    split_launch(qkvw, qkvh, qkvl, QKV_WN);
    split_launch(ow,   owh,  owl,  O_WN);
    split_launch(gw,   gwh,  gwl,  G_WN);
    split_launch(uw,   uwh,  uwl,  G_WN);
    split_launch(dw,   dwh,  dwl,  D_WN);
    split_launch(emb,  embh, embl, E_WN);

    embed_kernel<<<BT, 256>>>(idx, emb, x);

    for (int l = 0; l < NL; l++) {
        rmsnorm_split_kernel<<<BT, 256>>>(x, ln1 + (long long)l * DIM, hh, hl);
        gemm_bf<0><<<dim3(T3D / 128, BT / 128), 512, GEMM_SMEM>>>(
            hh, hl, qkvh + (long long)l * T3D * DIM, qkvl + (long long)l * T3D * DIM,
            qkv, nullptr, nullptr, T3D, DIM);
        flash_kernel<<<dim3(SEQT / 64, 16, 2), 256>>>(qkv, hh, hl);
        gemm_bf<1><<<dim3(DIM / 128, BT / 128), 512, GEMM_SMEM>>>(
            hh, hl, owh + (long long)l * DIM * DIM, owl + (long long)l * DIM * DIM,
            x, nullptr, nullptr, DIM, DIM);
        rmsnorm_split_kernel<<<BT, 256>>>(x, ln2 + (long long)l * DIM, hh, hl);
        gemm_bf<0><<<dim3(DIFF / 128, BT / 128), 512, GEMM_SMEM>>>(
            hh, hl, gwh + (long long)l * DIFF * DIM, gwl + (long long)l * DIFF * DIM,
            gate, nullptr, nullptr, DIFF, DIM);
        gemm_bf<2><<<dim3(DIFF / 128, BT / 128), 512, GEMM_SMEM>>>(
            hh, hl, uwh + (long long)l * DIFF * DIM, uwl + (long long)l * DIFF * DIM,
            gate, a2h, a2l, DIFF, DIM);
        gemm_bf<1><<<dim3(DIM / 128, BT / 128), 512, GEMM_SMEM>>>(
            a2h, a2l, dwh + (long long)l * DIM * DIFF, dwl + (long long)l * DIM * DIFF,
            x, nullptr, nullptr, DIM, DIFF);
    }

    rmsnorm_split_kernel<<<BT, 256>>>(x, lnf, hh, hl);
    gemm_bf<0><<<dim3(NVOC / 128, BT / 128), 512, GEMM_SMEM>>>(
        hh, hl, embh, embl, (float*)d_out, nullptr, nullptr, NVOC, DIM);
}